// round 8
// baseline (speedup 1.0000x reference)
#include <cuda_runtime.h>
#include <cuda_fp16.h>
#include <mma.h>
#include <cstdint>

using namespace nvcuda;

// Problem shape
constexpr int B = 16;
constexpr int N = 2048;
constexpr int D = 512;

// Tiling
constexpr int BM = 64;
constexpr int BN = 64;
constexpr int NT = N / BN;       // 32 key tiles
constexpr int MBLOCKS = N / BM;  // 32

// Padded smem leading dims
constexpr int QLD = D + 8;    // 520 halfs -> 1040B rows (breaks ldmatrix conflicts)
constexpr int SLD = BN + 4;   // 68 floats
constexpr int PLD = BN + 8;   // 72 halfs

// Shared memory layout (bytes)
constexpr int OFF_Q  = 0;
constexpr int SZ_T   = BM * QLD * 2;            // 66560 per Q/K tile
constexpr int OFF_K0 = OFF_Q + SZ_T;            // 66560
constexpr int OFF_K1 = OFF_K0 + SZ_T;           // 133120
constexpr int OFF_S  = OFF_K1 + SZ_T;           // 199680
constexpr int OFF_P  = OFF_S + BM * SLD * 4;    // 217088
constexpr int OFF_KN = OFF_P + BM * PLD * 2;    // 226304 (2 x 64 floats)
constexpr int OFF_L  = OFF_KN + 512;            // 226816
constexpr int SMEM_BYTES = OFF_L + 256;         // 227072 (<= 232448 limit)
// Epilogue O staging aliases Q+K0: 8 warps * 64*64 floats = 131072 <= 133120. OK.

// Scratch: normalized x (fp16) and per-row L2 norms
__device__ __half xn_g[(size_t)B * N * D];
__device__ float  norm_g[B * N];

__device__ __forceinline__ void cpasync16(uint32_t dst, const void* src) {
    asm volatile("cp.async.cg.shared.global [%0], [%1], 16;" :: "r"(dst), "l"(src));
}
__device__ __forceinline__ void cp_commit() { asm volatile("cp.async.commit_group;"); }
template <int K> __device__ __forceinline__ void cp_wait() {
    asm volatile("cp.async.wait_group %0;" :: "n"(K));
}

// ---------------------------------------------------------------------------
// Kernel 1: per-row L2 norm + fp16 normalize.  grid = B*N blocks, 128 threads.
// ---------------------------------------------------------------------------
__global__ void normalize_kernel(const float* __restrict__ x) {
    const int row = blockIdx.x;
    const float* xr = x + (size_t)row * D;
    const int t = threadIdx.x;

    float4 v = reinterpret_cast<const float4*>(xr)[t];
    float s = v.x * v.x + v.y * v.y + v.z * v.z + v.w * v.w;
    #pragma unroll
    for (int o = 16; o > 0; o >>= 1) s += __shfl_down_sync(0xffffffffu, s, o);

    __shared__ float ws[4];
    __shared__ float inv_sh;
    if ((t & 31) == 0) ws[t >> 5] = s;
    __syncthreads();
    if (t == 0) {
        float tot = ws[0] + ws[1] + ws[2] + ws[3];
        float nm = sqrtf(tot);
        norm_g[row] = nm;
        inv_sh = 1.0f / fmaxf(nm, 1e-20f);
    }
    __syncthreads();
    const float inv = inv_sh;

    __half2* o2 = reinterpret_cast<__half2*>(xn_g + (size_t)row * D);
    o2[2 * t + 0] = __floats2half2_rn(v.x * inv, v.y * inv);
    o2[2 * t + 1] = __floats2half2_rn(v.z * inv, v.w * inv);
}

// ---------------------------------------------------------------------------
// Kernel 2: pipelined fused attention.
// Per iteration t: softmax(t) (on S(t) from last iter) -> barrier ->
//   merged MMA region: S(t+1) interleaved with PV(t)   -> barrier.
// ---------------------------------------------------------------------------
__global__ void __launch_bounds__(256, 1)
attn_kernel(float* __restrict__ out) {
    extern __shared__ char smem[];
    __half* Qs   = reinterpret_cast<__half*>(smem + OFF_Q);
    __half* Ks0  = reinterpret_cast<__half*>(smem + OFF_K0);
    __half* Ks1  = reinterpret_cast<__half*>(smem + OFF_K1);
    float*  Ss   = reinterpret_cast<float*>(smem + OFF_S);
    __half* Ps   = reinterpret_cast<__half*>(smem + OFF_P);
    float*  knrm = reinterpret_cast<float*>(smem + OFF_KN);   // 2 x 64
    float*  lsh  = reinterpret_cast<float*>(smem + OFF_L);

    const uint32_t sK[2] = {
        (uint32_t)__cvta_generic_to_shared(Ks0),
        (uint32_t)__cvta_generic_to_shared(Ks1)
    };

    const int b  = blockIdx.x / MBLOCKS;
    const int m0 = (blockIdx.x % MBLOCKS) * BM;

    const __half* Xn = xn_g + (size_t)b * N * D;
    const float*  Nv = norm_g + (size_t)b * N;

    const int tid  = threadIdx.x;
    const int warp = tid >> 5;
    const int lane = tid & 31;

    const int sr0 = (warp >> 1) * 16;   // S rows this warp computes
    const int sc0 = (warp & 1) * 32;    // S cols this warp computes
    const int d0  = warp * 64;          // O column slice

    // cp.async K-tile loader: 64 rows * 64 segs of 16B, 16 per thread
    auto load_K = [&](int n0, int buf) {
        const char* src = reinterpret_cast<const char*>(Xn + (size_t)n0 * D);
        uint32_t dst = sK[buf];
        #pragma unroll
        for (int k = 0; k < 16; k++) {
            int i = tid + k * 256;
            int r = i >> 6, seg = i & 63;
            cpasync16(dst + r * (QLD * 2) + seg * 16,
                      src + (size_t)r * (D * 2) + seg * 16);
        }
    };

    // ---- prologue ----
    load_K(0, 0); cp_commit();
    load_K(BN, 1); cp_commit();

    {   // Q tile (plain loads) while K streams
        const int4* src = reinterpret_cast<const int4*>(Xn + (size_t)m0 * D);
        for (int i = tid; i < BM * (D / 8); i += 256) {
            int r = i >> 6, seg = i & 63;
            reinterpret_cast<int4*>(Qs + r * QLD)[seg] = src[i];
        }
    }
    if (tid < BM) { lsh[tid] = 0.0f; knrm[tid] = __ldg(&Nv[tid]); }

    // O accumulators
    wmma::fragment<wmma::accumulator, 16, 16, 16, float> ofrag[4][4];
    #pragma unroll
    for (int ri = 0; ri < 4; ri++)
        #pragma unroll
        for (int ci = 0; ci < 4; ci++)
            wmma::fill_fragment(ofrag[ri][ci], 0.0f);

    cp_wait<1>();          // K(0) resident (this thread)
    __syncthreads();       // K(0) + Q + knrm[0] visible to all

    // S(0) -> Ss
    {
        wmma::fragment<wmma::accumulator, 16, 16, 16, float> sacc[2];
        wmma::fill_fragment(sacc[0], 0.0f);
        wmma::fill_fragment(sacc[1], 0.0f);
        for (int k = 0; k < D; k += 16) {
            wmma::fragment<wmma::matrix_a, 16, 16, 16, __half, wmma::row_major> af;
            wmma::load_matrix_sync(af, Qs + sr0 * QLD + k, QLD);
            #pragma unroll
            for (int cc = 0; cc < 2; cc++) {
                wmma::fragment<wmma::matrix_b, 16, 16, 16, __half, wmma::col_major> bf;
                wmma::load_matrix_sync(bf, Ks0 + (sc0 + cc * 16) * QLD + k, QLD);
                wmma::mma_sync(sacc[cc], af, bf, sacc[cc]);
            }
        }
        wmma::store_matrix_sync(Ss + sr0 * SLD + sc0,      sacc[0], SLD, wmma::mem_row_major);
        wmma::store_matrix_sync(Ss + sr0 * SLD + sc0 + 16, sacc[1], SLD, wmma::mem_row_major);
    }
    __syncthreads();       // S(0) visible

    // ---- main loop ----
    for (int t = 0; t < NT; t++) {
        const bool doS = (t + 1 < NT);

        // Issue prefetch of K(t+1) (buffer freed by PV(t-1); for t=0 it's
        // already loaded in the prologue).
        if (t >= 1 && doS) { load_K((t + 1) * BN, (t + 1) & 1); cp_commit(); }

        // Prefetch key norms for tile t+1 (consumed next iteration)
        float knv = 0.0f;
        if (doS && tid < BN) knv = __ldg(&Nv[(t + 1) * BN + tid]);

        // ---- softmax(t): Ss -> Ps, accumulate l ----
        {
            const float* kn = knrm + (t & 1) * 64;
            const int r = tid >> 2;
            const int cseg = (tid & 3) * 16;
            float sum = 0.0f;
            #pragma unroll
            for (int c = 0; c < 16; c++) {
                float s = Ss[r * SLD + cseg + c];
                float e = __expf(s - 1.0f);
                sum += e;
                Ps[r * PLD + cseg + c] = __float2half(e * kn[cseg + c]);
            }
            sum += __shfl_down_sync(0xffffffffu, sum, 2, 4);
            sum += __shfl_down_sync(0xffffffffu, sum, 1, 4);
            if ((tid & 3) == 0) lsh[r] += sum;
        }
        if (doS && tid < BN) knrm[((t + 1) & 1) * 64 + tid] = knv;

        cp_wait<0>();          // K(t+1) resident (this thread)
        __syncthreads();       // Ps + K(t+1) + knrm(t+1) visible; Ss free

        // ---- merged MMA region: PV(t) interleaved with S(t+1) ----
        const __half* Kcur = ((t & 1) == 0) ? Ks0 : Ks1;
        const __half* Knxt = ((t & 1) == 0) ? Ks1 : Ks0;

        wmma::fragment<wmma::accumulator, 16, 16, 16, float> sacc[2];
        wmma::fill_fragment(sacc[0], 0.0f);
        wmma::fill_fragment(sacc[1], 0.0f);

        #pragma unroll
        for (int kk = 0; kk < 4; kk++) {
            const int kk16 = kk * 16;
            // PV sub-block
            {
                wmma::fragment<wmma::matrix_a, 16, 16, 16, __half, wmma::row_major> af[4];
                #pragma unroll
                for (int ri = 0; ri < 4; ri++)
                    wmma::load_matrix_sync(af[ri], Ps + (ri * 16) * PLD + kk16, PLD);
                #pragma unroll
                for (int ci = 0; ci < 4; ci++) {
                    wmma::fragment<wmma::matrix_b, 16, 16, 16, __half, wmma::row_major> bf;
                    wmma::load_matrix_sync(bf, Kcur + kk16 * QLD + d0 + ci * 16, QLD);
                    #pragma unroll
                    for (int ri = 0; ri < 4; ri++)
                        wmma::mma_sync(ofrag[ri][ci], af[ri], bf, ofrag[ri][ci]);
                }
            }
            // S(t+1) sub-block: K-range [kk*128, kk*128+128)
            if (doS) {
                #pragma unroll
                for (int j = 0; j < 8; j++) {
                    const int k = kk * 128 + j * 16;
                    wmma::fragment<wmma::matrix_a, 16, 16, 16, __half, wmma::row_major> af;
                    wmma::load_matrix_sync(af, Qs + sr0 * QLD + k, QLD);
                    #pragma unroll
                    for (int cc = 0; cc < 2; cc++) {
                        wmma::fragment<wmma::matrix_b, 16, 16, 16, __half, wmma::col_major> bf;
                        wmma::load_matrix_sync(bf, Knxt + (sc0 + cc * 16) * QLD + k, QLD);
                        wmma::mma_sync(sacc[cc], af, bf, sacc[cc]);
                    }
                }
            }
        }
        if (doS) {
            wmma::store_matrix_sync(Ss + sr0 * SLD + sc0,      sacc[0], SLD, wmma::mem_row_major);
            wmma::store_matrix_sync(Ss + sr0 * SLD + sc0 + 16, sacc[1], SLD, wmma::mem_row_major);
        }
        __syncthreads();       // region done: Ss(t+1) visible, Kcur/Ps free
    }

    // ---- epilogue: stage O in smem (aliases Q/K0), scale by 1/l, write ----
    float* Ost = reinterpret_cast<float*>(smem) + warp * (64 * 64);
    #pragma unroll
    for (int ri = 0; ri < 4; ri++)
        #pragma unroll
        for (int ci = 0; ci < 4; ci++)
            wmma::store_matrix_sync(Ost + ri * 16 * 64 + ci * 16, ofrag[ri][ci],
                                    64, wmma::mem_row_major);
    __syncwarp();

    float* outB = out + ((size_t)b * N + m0) * D;
    for (int i = lane; i < 64 * 16; i += 32) {
        int r  = i >> 4;
        int c4 = (i & 15) * 4;
        float inv = 1.0f / lsh[r];
        float4 v = *reinterpret_cast<float4*>(Ost + r * 64 + c4);
        v.x *= inv; v.y *= inv; v.z *= inv; v.w *= inv;
        *reinterpret_cast<float4*>(outB + (size_t)r * D + d0 + c4) = v;
    }
}

// ---------------------------------------------------------------------------
extern "C" void kernel_launch(void* const* d_in, const int* in_sizes, int n_in,
                              void* d_out, int out_size) {
    (void)in_sizes; (void)n_in; (void)out_size;
    const float* x = reinterpret_cast<const float*>(d_in[0]);
    float* out = reinterpret_cast<float*>(d_out);

    cudaFuncSetAttribute(attn_kernel,
                         cudaFuncAttributeMaxDynamicSharedMemorySize, SMEM_BYTES);

    normalize_kernel<<<B * N, 128>>>(x);
    attn_kernel<<<B * MBLOCKS, 256, SMEM_BYTES>>>(out);
}

// round 9
// speedup vs baseline: 1.2394x; 1.2394x over previous
#include <cuda_runtime.h>
#include <cuda_fp16.h>
#include <cstdint>

// Problem shape
constexpr int B = 16;
constexpr int N = 2048;
constexpr int D = 512;

// Tiling
constexpr int BM = 64;            // query rows per CTA
constexpr int BN = 128;           // key rows per tile (two 64-row halves)
constexpr int NT = N / BN;        // 16 key tiles
constexpr int MBLOCKS = N / BM;   // 32

// Padded leading dims (halfs). Stride must be an odd multiple of 16B.
constexpr int QLD = D + 8;        // 520 -> 1040B rows
constexpr int PLD = BN + 8;       // 136 -> 272B rows

// Shared memory layout (bytes)
constexpr int OFF_Q  = 0;
constexpr int SZ_Q   = BM * QLD * 2;        // 66560
constexpr int OFF_K  = OFF_Q + SZ_Q;        // 66560
constexpr int SZ_K   = BN * QLD * 2;        // 133120
constexpr int OFF_P  = OFF_K + SZ_K;        // 199680
constexpr int SZ_P   = BM * PLD * 2;        // 17408
constexpr int OFF_KN = OFF_P + SZ_P;        // 217088 (128 floats)
constexpr int OFF_L  = OFF_KN + 512;        // 217600 (64 floats)
constexpr int SMEM_BYTES = OFF_L + 256;     // 217856 (<= 232448)

// Scratch: normalized x (fp16) and per-row L2 norms
__device__ __half xn_g[(size_t)B * N * D];
__device__ float  norm_g[B * N];

// ---------------------------------------------------------------------------
// PTX helpers
// ---------------------------------------------------------------------------
__device__ __forceinline__ void cpasync16(uint32_t dst, const void* src) {
    asm volatile("cp.async.cg.shared.global [%0], [%1], 16;" :: "r"(dst), "l"(src));
}
__device__ __forceinline__ void cp_commit() { asm volatile("cp.async.commit_group;"); }
template <int K> __device__ __forceinline__ void cp_wait() {
    asm volatile("cp.async.wait_group %0;" :: "n"(K));
}
__device__ __forceinline__ void bar_sync(int id, int cnt) {
    asm volatile("bar.sync %0, %1;" :: "r"(id), "r"(cnt) : "memory");
}
__device__ __forceinline__ void ldsm4(uint32_t* r, uint32_t a) {
    asm volatile("ldmatrix.sync.aligned.m8n8.x4.shared.b16 {%0,%1,%2,%3}, [%4];"
                 : "=r"(r[0]), "=r"(r[1]), "=r"(r[2]), "=r"(r[3]) : "r"(a));
}
__device__ __forceinline__ void ldsm4t(uint32_t* r, uint32_t a) {
    asm volatile("ldmatrix.sync.aligned.m8n8.x4.trans.shared.b16 {%0,%1,%2,%3}, [%4];"
                 : "=r"(r[0]), "=r"(r[1]), "=r"(r[2]), "=r"(r[3]) : "r"(a));
}
__device__ __forceinline__ void mma16816(float* c, const uint32_t* a,
                                         uint32_t b0, uint32_t b1) {
    asm volatile(
        "mma.sync.aligned.m16n8k16.row.col.f32.f16.f16.f32 "
        "{%0,%1,%2,%3},{%4,%5,%6,%7},{%8,%9},{%0,%1,%2,%3};"
        : "+f"(c[0]), "+f"(c[1]), "+f"(c[2]), "+f"(c[3])
        : "r"(a[0]), "r"(a[1]), "r"(a[2]), "r"(a[3]), "r"(b0), "r"(b1));
}
// ldmatrix x4 address: tiles [r0-7|c0-7, r8-15|c0-7, r0-7|c8-15, r8-15|c8-15]
__device__ __forceinline__ uint32_t ldsm_addr(uint32_t base, int row, int col,
                                              int ld, int lane) {
    int r = row + (lane & 15);
    int c = col + ((lane >> 4) << 3);
    return base + (uint32_t)(r * ld + c) * 2;
}

// ---------------------------------------------------------------------------
// Kernel 1: per-row L2 norm + fp16 normalize.  grid = B*N blocks, 128 threads.
// ---------------------------------------------------------------------------
__global__ void normalize_kernel(const float* __restrict__ x) {
    const int row = blockIdx.x;
    const float* xr = x + (size_t)row * D;
    const int t = threadIdx.x;

    float4 v = reinterpret_cast<const float4*>(xr)[t];
    float s = v.x * v.x + v.y * v.y + v.z * v.z + v.w * v.w;
    #pragma unroll
    for (int o = 16; o > 0; o >>= 1) s += __shfl_down_sync(0xffffffffu, s, o);

    __shared__ float ws[4];
    __shared__ float inv_sh;
    if ((t & 31) == 0) ws[t >> 5] = s;
    __syncthreads();
    if (t == 0) {
        float tot = ws[0] + ws[1] + ws[2] + ws[3];
        float nm = sqrtf(tot);
        norm_g[row] = nm;
        inv_sh = 1.0f / fmaxf(nm, 1e-20f);
    }
    __syncthreads();
    const float inv = inv_sh;

    __half2* o2 = reinterpret_cast<__half2*>(xn_g + (size_t)row * D);
    o2[2 * t + 0] = __floats2half2_rn(v.x * inv, v.y * inv);
    o2[2 * t + 1] = __floats2half2_rn(v.z * inv, v.w * inv);
}

// ---------------------------------------------------------------------------
// Kernel 2: fused attention, manual mma + register softmax.
// grid = B * (N/BM) = 512 CTAs, 256 threads (8 warps).
// ---------------------------------------------------------------------------
__global__ void __launch_bounds__(256, 1)
attn_kernel(float* __restrict__ out) {
    extern __shared__ char smem[];
    __half* Qs   = reinterpret_cast<__half*>(smem + OFF_Q);
    float*  knrm = reinterpret_cast<float*>(smem + OFF_KN);
    float*  lsh  = reinterpret_cast<float*>(smem + OFF_L);
    const uint32_t Qu = (uint32_t)__cvta_generic_to_shared(smem + OFF_Q);
    const uint32_t Ku = (uint32_t)__cvta_generic_to_shared(smem + OFF_K);
    const uint32_t Pu = (uint32_t)__cvta_generic_to_shared(smem + OFF_P);
    __half* Ps = reinterpret_cast<__half*>(smem + OFF_P);

    const int b  = blockIdx.x / MBLOCKS;
    const int m0 = (blockIdx.x % MBLOCKS) * BM;

    const __half* Xn = xn_g + (size_t)b * N * D;
    const float*  Nv = norm_g + (size_t)b * N;

    const int tid  = threadIdx.x;
    const int warp = tid >> 5;
    const int lane = tid & 31;

    // S-phase warp tile: 32 rows x 32 keys; 2x4 warp grid over 64x128
    const int sr0 = 32 * (warp >> 2);
    const int sn0 = 32 * (warp & 3);
    const bool grpA = (warp & 3) < 2;                 // warps whose S keys are in half A
    const int gtid = ((warp >> 2) * 2 + (warp & 1)) * 32 + lane;   // 0..127 in group
    const int d0 = warp * 64;                         // PV D-slice

    // group half-tile loader: 64 rows x 64 segs(16B) over 128 threads = 32 each
    auto load_Khalf = [&](int keybase, int half) {
        const char* src = reinterpret_cast<const char*>(Xn + (size_t)(keybase + half * 64) * D);
        uint32_t dst = Ku + (uint32_t)(half * 64 * QLD) * 2;
        #pragma unroll
        for (int i = 0; i < 32; i++) {
            int idx = gtid + i * 128;
            int r = idx >> 6, sg = idx & 63;
            cpasync16(dst + (uint32_t)(r * QLD + sg * 8) * 2,
                      src + (size_t)r * (D * 2) + sg * 16);
        }
    };

    // ---- prologue: K(0) full tile (all threads), Q, norms, l ----
    {
        const char* src = reinterpret_cast<const char*>(Xn);
        #pragma unroll
        for (int i = 0; i < 32; i++) {
            int idx = tid + i * 256;
            int r = idx >> 6, sg = idx & 63;
            cpasync16(Ku + (uint32_t)(r * QLD + sg * 8) * 2,
                      src + (size_t)r * (D * 2) + sg * 16);
        }
        cp_commit();
        const int4* qsrc = reinterpret_cast<const int4*>(Xn + (size_t)m0 * D);
        for (int i = tid; i < BM * (D / 8); i += 256) {
            int r = i >> 6, seg = i & 63;
            reinterpret_cast<int4*>(Qs + r * QLD)[seg] = qsrc[i];
        }
        if (tid < BM) lsh[tid] = 0.0f;
        if (tid < BN) knrm[tid] = __ldg(&Nv[tid]);
        cp_wait<0>();
        __syncthreads();
    }

    // O accumulators: 4 row-frags x 8 col-octets x 4 f32 (128 regs), live all loop
    float o[4][8][4];
    #pragma unroll
    for (int rf = 0; rf < 4; rf++)
        #pragma unroll
        for (int nf = 0; nf < 8; nf++)
            #pragma unroll
            for (int q = 0; q < 4; q++) o[rf][nf][q] = 0.0f;

    for (int t = 0; t < NT; t++) {
        // ==== S phase: sacc[rf][nf] = Q(32 rows) x K^T(32 keys) ====
        float sacc[2][4][4];
        #pragma unroll
        for (int rf = 0; rf < 2; rf++)
            #pragma unroll
            for (int nf = 0; nf < 4; nf++)
                #pragma unroll
                for (int q = 0; q < 4; q++) sacc[rf][nf][q] = 0.0f;

        #pragma unroll 8
        for (int k = 0; k < D; k += 16) {
            uint32_t a0[4], a1[4], b0[4], b1[4];
            ldsm4(a0, ldsm_addr(Qu, sr0,      k, QLD, lane));
            ldsm4(a1, ldsm_addr(Qu, sr0 + 16, k, QLD, lane));
            ldsm4(b0, ldsm_addr(Ku, sn0,      k, QLD, lane));   // keys sn0..+15
            ldsm4(b1, ldsm_addr(Ku, sn0 + 16, k, QLD, lane));   // keys +16..+31
            mma16816(sacc[0][0], a0, b0[0], b0[2]);
            mma16816(sacc[0][1], a0, b0[1], b0[3]);
            mma16816(sacc[0][2], a0, b1[0], b1[2]);
            mma16816(sacc[0][3], a0, b1[1], b1[3]);
            mma16816(sacc[1][0], a1, b0[0], b0[2]);
            mma16816(sacc[1][1], a1, b0[1], b0[3]);
            mma16816(sacc[1][2], a1, b1[0], b1[2]);
            mma16816(sacc[1][3], a1, b1[1], b1[3]);
        }

        // ==== register softmax: e = exp(s-1); P = e * |x_j|; l += rowsum(e) ====
        #pragma unroll
        for (int rf = 0; rf < 2; rf++) {
            float rs0 = 0.0f, rs1 = 0.0f;
            const int rr = sr0 + rf * 16 + (lane >> 2);
            #pragma unroll
            for (int nf = 0; nf < 4; nf++) {
                const int n = sn0 + nf * 8 + 2 * (lane & 3);
                const float kn0 = knrm[n], kn1 = knrm[n + 1];
                float e0 = __expf(sacc[rf][nf][0] - 1.0f);
                float e1 = __expf(sacc[rf][nf][1] - 1.0f);
                float e2 = __expf(sacc[rf][nf][2] - 1.0f);
                float e3 = __expf(sacc[rf][nf][3] - 1.0f);
                rs0 += e0 + e1;
                rs1 += e2 + e3;
                *reinterpret_cast<__half2*>(&Ps[rr * PLD + n]) =
                    __floats2half2_rn(e0 * kn0, e1 * kn1);
                *reinterpret_cast<__half2*>(&Ps[(rr + 8) * PLD + n]) =
                    __floats2half2_rn(e2 * kn0, e3 * kn1);
            }
            rs0 += __shfl_xor_sync(0xffffffffu, rs0, 1, 4);
            rs0 += __shfl_xor_sync(0xffffffffu, rs0, 2, 4);
            rs1 += __shfl_xor_sync(0xffffffffu, rs1, 1, 4);
            rs1 += __shfl_xor_sync(0xffffffffu, rs1, 2, 4);
            if ((lane & 3) == 0) {
                atomicAdd(&lsh[rr], rs0);
                atomicAdd(&lsh[rr + 8], rs1);
            }
        }
        __syncthreads();    // P visible to all; K(t) still live

        float knv = 0.0f;

        // ==== PV half A: keys 0..63 of this tile ====
        #pragma unroll
        for (int kk = 0; kk < 64; kk += 16) {
            uint32_t pa[4][4];
            #pragma unroll
            for (int rf = 0; rf < 4; rf++)
                ldsm4(pa[rf], ldsm_addr(Pu, rf * 16, kk, PLD, lane));
            #pragma unroll
            for (int g = 0; g < 4; g++) {
                uint32_t vb[4];
                ldsm4t(vb, ldsm_addr(Ku, kk, d0 + g * 16, QLD, lane));
                #pragma unroll
                for (int rf = 0; rf < 4; rf++) {
                    mma16816(o[rf][2 * g + 0], pa[rf], vb[0], vb[1]);
                    mma16816(o[rf][2 * g + 1], pa[rf], vb[2], vb[3]);
                }
            }
        }
        __syncthreads();    // all warps done reading K half A
        if (t + 1 < NT && grpA) {
            load_Khalf((t + 1) * BN, 0);
            cp_commit();
            if (gtid < 64) knv = __ldg(&Nv[(t + 1) * BN + gtid]);
        }

        // ==== PV half B: keys 64..127 (overlaps KA' load) ====
        #pragma unroll
        for (int kk = 64; kk < 128; kk += 16) {
            uint32_t pa[4][4];
            #pragma unroll
            for (int rf = 0; rf < 4; rf++)
                ldsm4(pa[rf], ldsm_addr(Pu, rf * 16, kk, PLD, lane));
            #pragma unroll
            for (int g = 0; g < 4; g++) {
                uint32_t vb[4];
                ldsm4t(vb, ldsm_addr(Ku, kk, d0 + g * 16, QLD, lane));
                #pragma unroll
                for (int rf = 0; rf < 4; rf++) {
                    mma16816(o[rf][2 * g + 0], pa[rf], vb[0], vb[1]);
                    mma16816(o[rf][2 * g + 1], pa[rf], vb[2], vb[3]);
                }
            }
        }
        __syncthreads();    // all warps done reading K half B; P free

        if (t + 1 < NT) {
            if (!grpA) {
                load_Khalf((t + 1) * BN, 1);
                cp_commit();
                if (gtid < 64) knv = __ldg(&Nv[(t + 1) * BN + 64 + gtid]);
            }
            cp_wait<0>();   // own group's half complete
            if (gtid < 64) knrm[(grpA ? 0 : 64) + gtid] = knv;
            bar_sync(grpA ? 1 : 2, 128);   // group-local: half + norms visible
        }
    }

    // ==== epilogue: scale by 1/l, direct global float2 stores ====
    float* outB = out + ((size_t)b * N + m0) * D;
    #pragma unroll
    for (int rf = 0; rf < 4; rf++) {
        const int rr = rf * 16 + (lane >> 2);
        const float i0 = 1.0f / lsh[rr];
        const float i1 = 1.0f / lsh[rr + 8];
        #pragma unroll
        for (int nf = 0; nf < 8; nf++) {
            const int cc = d0 + nf * 8 + 2 * (lane & 3);
            float2 v0 = make_float2(o[rf][nf][0] * i0, o[rf][nf][1] * i0);
            float2 v1 = make_float2(o[rf][nf][2] * i1, o[rf][nf][3] * i1);
            *reinterpret_cast<float2*>(&outB[(size_t)rr * D + cc]) = v0;
            *reinterpret_cast<float2*>(&outB[(size_t)(rr + 8) * D + cc]) = v1;
        }
    }
}

// ---------------------------------------------------------------------------
extern "C" void kernel_launch(void* const* d_in, const int* in_sizes, int n_in,
                              void* d_out, int out_size) {
    (void)in_sizes; (void)n_in; (void)out_size;
    const float* x = reinterpret_cast<const float*>(d_in[0]);
    float* out = reinterpret_cast<float*>(d_out);

    cudaFuncSetAttribute(attn_kernel,
                         cudaFuncAttributeMaxDynamicSharedMemorySize, SMEM_BYTES);

    normalize_kernel<<<B * N, 128>>>(x);
    attn_kernel<<<B * MBLOCKS, 256, SMEM_BYTES>>>(out);
}